// round 13
// baseline (speedup 1.0000x reference)
#include <cuda_runtime.h>
#include <cuda_fp16.h>
#include <cstdint>

#define B_ 16
#define S_ 2048
#define D_ 1024
#define H_ 128
#define M_TOT (B_*S_)

// ---------------- scratch (__device__ globals; allocation-free rule) -------
__device__ __half g_wt[3 * H_ * D_];             // W single fp16, [z][n][k]
__device__ __half g_q[M_TOT * H_];               // Q single (scaled)
__device__ __half g_k[M_TOT * H_];               // K single
__device__ __half g_v[M_TOT * H_];               // V single

// ---------------- helpers (sm_80-baseline, family-target safe) -------------
__device__ __forceinline__ uint32_t smem_u32(const void* p) {
    uint32_t a;
    asm("{ .reg .u64 t; cvta.to.shared.u64 t, %1; cvt.u32.u64 %0, t; }"
        : "=r"(a) : "l"(p));
    return a;
}
__device__ __forceinline__ void cp16(uint32_t dst, const void* src) {
    asm volatile("cp.async.cg.shared.global [%0], [%1], 16;" :: "r"(dst), "l"(src));
}
#define CP_COMMIT() asm volatile("cp.async.commit_group;" ::: "memory")
#define CP_WAIT0()  asm volatile("cp.async.wait_group 0;" ::: "memory")
#define CP_WAIT1()  asm volatile("cp.async.wait_group 1;" ::: "memory")

__device__ __forceinline__ void ldsm_x4(uint32_t r[4], uint32_t addr) {
    asm volatile("ldmatrix.sync.aligned.m8n8.x4.shared.b16 {%0,%1,%2,%3}, [%4];"
        : "=r"(r[0]), "=r"(r[1]), "=r"(r[2]), "=r"(r[3]) : "r"(addr));
}
__device__ __forceinline__ void ldsm_x4_t(uint32_t r[4], uint32_t addr) {
    asm volatile("ldmatrix.sync.aligned.m8n8.x4.trans.shared.b16 {%0,%1,%2,%3}, [%4];"
        : "=r"(r[0]), "=r"(r[1]), "=r"(r[2]), "=r"(r[3]) : "r"(addr));
}
__device__ __forceinline__ void mma16816(float c[4], const uint32_t a[4],
                                         const uint32_t b[2]) {
    asm volatile("mma.sync.aligned.m16n8k16.row.col.f32.f16.f16.f32 "
        "{%0,%1,%2,%3}, {%4,%5,%6,%7}, {%8,%9}, {%0,%1,%2,%3};"
        : "+f"(c[0]), "+f"(c[1]), "+f"(c[2]), "+f"(c[3])
        : "r"(a[0]), "r"(a[1]), "r"(a[2]), "r"(a[3]), "r"(b[0]), "r"(b[1]));
}
__device__ __forceinline__ uint32_t pack2h(float x0, float x1) {
    __half2 p = __floats2half2_rn(x0, x1);
    return *(uint32_t*)&p;
}
__device__ __forceinline__ float ex2f(float x) {
    float y;
    asm("ex2.approx.f32 %0, %1;" : "=f"(y) : "f"(x));
    return y;
}

// ---------------------------------------------------------------------------
// Kernel 0: W [1024,128] fp32 -> transposed single fp16 [z][128][1024]
// smem-staged transpose: coalesced reads AND coalesced 16B writes.
// grid (8, 3): 128-k block x z.  256 threads.
// ---------------------------------------------------------------------------
__global__ __launch_bounds__(256) void convert_w_kernel(
    const float* __restrict__ Wq, const float* __restrict__ Wk,
    const float* __restrict__ Wv)
{
    __shared__ __half t[128][136];               // pad 136 halfs: 16B-aligned rows
    const int z = blockIdx.y, kb = blockIdx.x;
    const float* W = (z == 0) ? Wq : (z == 1) ? Wk : Wv;
    const int tid = threadIdx.x;

    #pragma unroll
    for (int i = 0; i < 64; i++) {
        int u = tid + i * 256;                   // 0..16383
        int k = u >> 7, n = u & 127;
        t[n][k] = __float2half_rn(W[(size_t)(kb * 128 + k) * H_ + n]);
    }
    __syncthreads();
    #pragma unroll
    for (int i = 0; i < 8; i++) {
        int u = tid + i * 256;                   // 0..2047 uint4 chunks
        int n = u >> 4, c = u & 15;
        uint4 v = *(const uint4*)&t[n][c * 8];
        *(uint4*)(g_wt + (size_t)(z * H_ + n) * D_ + kb * 128 + c * 8) = v;
    }
}

// ---------------------------------------------------------------------------
// Kernel 1: QKV projection, single fp16 both operands (A converted in-reg).
// CTA: 128x128, 8 warps, grid interleave (m*3+z) for L2 A-reuse, 2 CTAs/SM.
// mt0 = m-tile offset (batch-group pipelining).
// ---------------------------------------------------------------------------
#define KST 144
#define QA 0
#define QW 18432
#define QKV_SMEM 36864

__global__ __launch_bounds__(256, 2) void qkv_gemm(const float* __restrict__ A,
                                                   int mt0)
{
    extern __shared__ char smc[];
    const uint32_t sb = smem_u32(smc);
    const int tid = threadIdx.x, lane = tid & 31, wid = tid >> 5;
    const int wm = wid >> 1, wn = wid & 1;
    const int m0 = (mt0 + blockIdx.x / 3) * 128, z = blockIdx.x % 3;
    const int g = lane >> 2, tg = lane & 3;

    const __half* wt = g_wt + (size_t)z * H_ * D_;

    float acc[2][8][4];
    #pragma unroll
    for (int a = 0; a < 2; a++)
        #pragma unroll
        for (int b = 0; b < 8; b++)
            #pragma unroll
            for (int c = 0; c < 4; c++) acc[a][b][c] = 0.f;

    for (int ch = 0; ch < 16; ch++) {
        const int k0 = ch * 64;
        #pragma unroll
        for (int i = 0; i < 4; i++) {
            const int rem = tid + i * 256;
            const int row = rem >> 3, c = rem & 7;
            cp16(sb + QW + row * KST + c * 16,
                 wt + (size_t)row * D_ + k0 + c * 8);
        }
        CP_COMMIT();

        #pragma unroll
        for (int gi = 0; gi < 4; gi++) {
            const int u = tid + gi * 256;
            const int row = u >> 3, c8 = u & 7;
            const float* ap = A + (size_t)(m0 + row) * D_ + k0 + c8 * 8;
            float4 f0 = *(const float4*)ap;
            float4 f1 = *(const float4*)(ap + 4);
            uint4 hv = make_uint4(pack2h(f0.x, f0.y), pack2h(f0.z, f0.w),
                                  pack2h(f1.x, f1.y), pack2h(f1.z, f1.w));
            *(uint4*)(smc + QA + row * KST + c8 * 16) = hv;
        }
        CP_WAIT0();
        __syncthreads();

        #pragma unroll
        for (int s = 0; s < 4; s++) {
            uint32_t af[2][4];
            #pragma unroll
            for (int mt = 0; mt < 2; mt++) {
                uint32_t ar = (uint32_t)((wm * 32 + mt * 16 + (lane & 15)) * KST
                               + (s * 16 + (lane >> 4) * 8) * 2);
                ldsm_x4(af[mt], sb + QA + ar);
            }
            uint32_t bw[4][4];
            #pragma unroll
            for (int p = 0; p < 4; p++) {
                uint32_t br = (uint32_t)((wn * 64 + p * 16 + (lane >> 4) * 8 + (lane & 7)) * KST
                               + (s * 16 + ((lane >> 3) & 1) * 8) * 2);
                ldsm_x4(bw[p], sb + QW + br);
            }
            #pragma unroll
            for (int p = 0; p < 4; p++)
                #pragma unroll
                for (int mt = 0; mt < 2; mt++) {
                    mma16816(acc[mt][2*p],   af[mt], bw[p]);
                    mma16816(acc[mt][2*p+1], af[mt], bw[p] + 2);
                }
        }
        __syncthreads();
    }

    const float scl = (z == 0)
        ? (0.0883883476483184405f * 1.4426950408889634f) : 1.0f;
    __half* dst = (z == 0) ? g_q : (z == 1) ? g_k : g_v;

    #pragma unroll
    for (int mt = 0; mt < 2; mt++)
        #pragma unroll
        for (int nt = 0; nt < 8; nt++) {
            float c0 = acc[mt][nt][0] * scl, c1 = acc[mt][nt][1] * scl;
            float c2 = acc[mt][nt][2] * scl, c3 = acc[mt][nt][3] * scl;
            int r0  = m0 + wm * 32 + mt * 16 + g;
            int col = wn * 64 + nt * 8 + tg * 2;
            *(uint32_t*)(dst + (size_t)r0 * H_ + col)       = pack2h(c0, c1);
            *(uint32_t*)(dst + (size_t)(r0 + 8) * H_ + col) = pack2h(c2, c3);
        }
}

// ---------------------------------------------------------------------------
// Kernel 2: causal flash attention, all-single fp16 operands.
// CTA = 128 queries, 8 warps, key tiles of 64, Q fragments in registers,
// 2-stage K/V pipeline, exp2 softmax.  b0 = batch offset (pipelining).
// ---------------------------------------------------------------------------
#define QS 272
#define ASTG  34816
#define AK 0
#define AV 17408
#define ATT_SMEM (2*ASTG)        // 69632

__global__ __launch_bounds__(256, 1) void attn_mma(float* __restrict__ out, int b0)
{
    extern __shared__ char smc[];
    const uint32_t sb = smem_u32(smc);
    const int tid = threadIdx.x, lane = tid & 31, w = tid >> 5;
    const int b  = b0 + blockIdx.y;
    const int it = 15 - blockIdx.x;          // heavy tiles first
    const int q0 = it * 128;
    const int jmax = 2 * it + 1;
    const int g = lane >> 2, tg = lane & 3;
    const size_t base = (size_t)b * S_ * H_;

    #define ATT_ISSUE_KV(j, st) do {                                          \
        const int t0_ = (j) * 64;                                             \
        const uint32_t s0_ = sb + (st) * ASTG;                                \
        _Pragma("unroll")                                                     \
        for (int i = 0; i < 8; i++) {                                         \
            const int buf = i >> 2;                                           \
            const int rem = tid + (i & 3) * 256;                              \
            const int row = rem >> 4, c = rem & 15;                           \
            uint32_t d = s0_ + buf * 17408 + row * QS + c * 16;               \
            const __half* src = (buf == 0 ? g_k : g_v) + base                 \
                                + (size_t)(t0_ + row) * H_ + c * 8;           \
            cp16(d, src);                                                     \
        }                                                                     \
    } while (0)

    #pragma unroll
    for (int i = 0; i < 8; i++) {
        const int rem = tid + i * 256;
        const int row = rem >> 4, c = rem & 15;
        cp16(sb + row * QS + c * 16,
             g_q + base + (size_t)(q0 + row) * H_ + c * 8);
    }
    CP_COMMIT(); CP_WAIT0();
    __syncthreads();
    uint32_t qf[8][4];
    #pragma unroll
    for (int ks = 0; ks < 8; ks++) {
        uint32_t ar = (uint32_t)((w * 16 + (lane & 15)) * QS
                       + (ks * 16 + (lane >> 4) * 8) * 2);
        ldsm_x4(qf[ks], sb + ar);
    }
    __syncthreads();

    ATT_ISSUE_KV(0, 0); CP_COMMIT();

    float o[16][4];
    #pragma unroll
    for (int f = 0; f < 16; f++)
        #pragma unroll
        for (int c = 0; c < 4; c++) o[f][c] = 0.f;
    float m0r = -INFINITY, m1r = -INFINITY, l0 = 0.f, l1 = 0.f;

    for (int j = 0; j <= jmax; j++) {
        if (j < jmax) { ATT_ISSUE_KV(j + 1, (j + 1) & 1); CP_COMMIT(); CP_WAIT1(); }
        else CP_WAIT0();
        __syncthreads();

        const int t0 = j * 64;
        const uint32_t stb = sb + (j & 1) * ASTG;

        if (t0 <= q0 + w * 16 + 15) {
            float s[8][4];
            #pragma unroll
            for (int nt = 0; nt < 8; nt++)
                #pragma unroll
                for (int c = 0; c < 4; c++) s[nt][c] = 0.f;

            #pragma unroll
            for (int ks = 0; ks < 8; ks++) {
                uint32_t bk[4][4];
                #pragma unroll
                for (int p = 0; p < 4; p++) {
                    uint32_t br = (uint32_t)((p * 16 + (lane >> 4) * 8 + (lane & 7)) * QS
                                   + (ks * 16 + ((lane >> 3) & 1) * 8) * 2);
                    ldsm_x4(bk[p], stb + AK + br);
                }
                #pragma unroll
                for (int p = 0; p < 4; p++) {
                    mma16816(s[2*p],   qf[ks], bk[p]);
                    mma16816(s[2*p+1], qf[ks], bk[p] + 2);
                }
            }

            if (j >= jmax - 1) {
                int r0 = q0 + w * 16 + g, r1 = r0 + 8;
                #pragma unroll
                for (int nt = 0; nt < 8; nt++) {
                    int kc = t0 + nt * 8 + tg * 2;
                    if (kc     > r0) s[nt][0] = -INFINITY;
                    if (kc + 1 > r0) s[nt][1] = -INFINITY;
                    if (kc     > r1) s[nt][2] = -INFINITY;
                    if (kc + 1 > r1) s[nt][3] = -INFINITY;
                }
            }

            float ml0 = -INFINITY, ml1 = -INFINITY;
            #pragma unroll
            for (int nt = 0; nt < 8; nt++) {
                ml0 = fmaxf(ml0, fmaxf(s[nt][0], s[nt][1]));
                ml1 = fmaxf(ml1, fmaxf(s[nt][2], s[nt][3]));
            }
            #pragma unroll
            for (int ofs = 1; ofs <= 2; ofs <<= 1) {
                ml0 = fmaxf(ml0, __shfl_xor_sync(0xffffffffu, ml0, ofs));
                ml1 = fmaxf(ml1, __shfl_xor_sync(0xffffffffu, ml1, ofs));
            }
            float mn0 = fmaxf(m0r, ml0), mn1 = fmaxf(m1r, ml1);
            float a0 = ex2f(m0r - mn0), a1 = ex2f(m1r - mn1);
            m0r = mn0; m1r = mn1;

            float rs0 = 0.f, rs1 = 0.f;
            #pragma unroll
            for (int nt = 0; nt < 8; nt++) {
                s[nt][0] = ex2f(s[nt][0] - mn0); rs0 += s[nt][0];
                s[nt][1] = ex2f(s[nt][1] - mn0); rs0 += s[nt][1];
                s[nt][2] = ex2f(s[nt][2] - mn1); rs1 += s[nt][2];
                s[nt][3] = ex2f(s[nt][3] - mn1); rs1 += s[nt][3];
            }
            l0 = l0 * a0 + rs0;
            l1 = l1 * a1 + rs1;
            #pragma unroll
            for (int f = 0; f < 16; f++) {
                o[f][0] *= a0; o[f][1] *= a0;
                o[f][2] *= a1; o[f][3] *= a1;
            }

            uint32_t pf[4][4];
            #pragma unroll
            for (int s4 = 0; s4 < 4; s4++) {
                pf[s4][0] = pack2h(s[2*s4][0],   s[2*s4][1]);
                pf[s4][1] = pack2h(s[2*s4][2],   s[2*s4][3]);
                pf[s4][2] = pack2h(s[2*s4+1][0], s[2*s4+1][1]);
                pf[s4][3] = pack2h(s[2*s4+1][2], s[2*s4+1][3]);
            }

            #pragma unroll
            for (int s4 = 0; s4 < 4; s4++) {
                #pragma unroll
                for (int half = 0; half < 2; half++) {
                    uint32_t vv[4][4];
                    #pragma unroll
                    for (int p4 = 0; p4 < 4; p4++) {
                        int p = half * 4 + p4;
                        uint32_t vr = (uint32_t)((s4 * 16 + (lane & 7) + ((lane >> 3) & 1) * 8) * QS
                                       + (p * 2 + (lane >> 4)) * 16);
                        ldsm_x4_t(vv[p4], stb + AV + vr);
                    }
                    #pragma unroll
                    for (int p4 = 0; p4 < 4; p4++) {
                        int p = half * 4 + p4;
                        mma16816(o[2*p],   pf[s4], vv[p4]);
                        mma16816(o[2*p+1], pf[s4], vv[p4] + 2);
                    }
                }
            }
        }
        __syncthreads();
    }

    #pragma unroll
    for (int ofs = 1; ofs <= 2; ofs <<= 1) {
        l0 += __shfl_xor_sync(0xffffffffu, l0, ofs);
        l1 += __shfl_xor_sync(0xffffffffu, l1, ofs);
    }
    float i0 = 1.f / l0, i1 = 1.f / l1;
    int r0 = q0 + w * 16 + g;
    #pragma unroll
    for (int f = 0; f < 16; f++) {
        float2 v0 = make_float2(o[f][0] * i0, o[f][1] * i0);
        float2 v1 = make_float2(o[f][2] * i1, o[f][3] * i1);
        *(float2*)(out + base + (size_t)r0 * H_ + f * 8 + tg * 2)       = v0;
        *(float2*)(out + base + (size_t)(r0 + 8) * H_ + f * 8 + tg * 2) = v1;
    }
}

// ---------------------------------------------------------------------------
// Launch: 4 batch-groups pipelined across 2 streams (capture-safe fork-join).
// Group g: qkv(batches 4g..4g+3) on stream0 -> event -> attn(same batches)
// on stream1, overlapping with qkv of group g+1 on stream0.
// ---------------------------------------------------------------------------
#define NGRP 4

extern "C" void kernel_launch(void* const* d_in, const int* in_sizes, int n_in,
                              void* d_out, int out_size)
{
    const float* input = (const float*)d_in[0];
    const float* Wq    = (const float*)d_in[1];
    const float* Wk    = (const float*)d_in[2];
    const float* Wv    = (const float*)d_in[3];
    float* out = (float*)d_out;

    static bool inited = false;
    static cudaStream_t s1;
    static cudaEvent_t evq[NGRP], evj;
    if (!inited) {
        cudaStreamCreateWithFlags(&s1, cudaStreamNonBlocking);
        for (int i = 0; i < NGRP; i++)
            cudaEventCreateWithFlags(&evq[i], cudaEventDisableTiming);
        cudaEventCreateWithFlags(&evj, cudaEventDisableTiming);
        cudaFuncSetAttribute(qkv_gemm, cudaFuncAttributeMaxDynamicSharedMemorySize, QKV_SMEM);
        cudaFuncSetAttribute(attn_mma, cudaFuncAttributeMaxDynamicSharedMemorySize, ATT_SMEM);
        inited = true;
    }

    convert_w_kernel<<<dim3(8, 3), 256>>>(Wq, Wk, Wv);

    const int mtiles_per_grp = (M_TOT / 128) / NGRP;      // 64
    const int batches_per_grp = B_ / NGRP;                // 4
    for (int g = 0; g < NGRP; g++) {
        qkv_gemm<<<3 * mtiles_per_grp, 256, QKV_SMEM>>>(input, g * mtiles_per_grp);
        cudaEventRecord(evq[g], 0);
        cudaStreamWaitEvent(s1, evq[g], 0);
        attn_mma<<<dim3(16, batches_per_grp), 256, ATT_SMEM, s1>>>(out, g * batches_per_grp);
    }
    cudaEventRecord(evj, s1);
    cudaStreamWaitEvent(0, evj, 0);
}

// round 14
// speedup vs baseline: 1.7215x; 1.7215x over previous
#include <cuda_runtime.h>
#include <cuda_fp16.h>
#include <cstdint>

#define B_ 16
#define S_ 2048
#define D_ 1024
#define H_ 128
#define M_TOT (B_*S_)

// ---------------- scratch (__device__ globals; allocation-free rule) -------
__device__ __half g_wt[3 * H_ * D_];             // W single fp16, [z][n][k]
__device__ __half g_q[M_TOT * H_];               // Q single (scaled)
__device__ __half g_k[M_TOT * H_];               // K single
__device__ __half g_v[M_TOT * H_];               // V single

// ---------------- helpers (sm_80-baseline, family-target safe) -------------
__device__ __forceinline__ uint32_t smem_u32(const void* p) {
    uint32_t a;
    asm("{ .reg .u64 t; cvta.to.shared.u64 t, %1; cvt.u32.u64 %0, t; }"
        : "=r"(a) : "l"(p));
    return a;
}
__device__ __forceinline__ void cp16(uint32_t dst, const void* src) {
    asm volatile("cp.async.cg.shared.global [%0], [%1], 16;" :: "r"(dst), "l"(src));
}
#define CP_COMMIT() asm volatile("cp.async.commit_group;" ::: "memory")
#define CP_WAIT0()  asm volatile("cp.async.wait_group 0;" ::: "memory")
#define CP_WAIT1()  asm volatile("cp.async.wait_group 1;" ::: "memory")

__device__ __forceinline__ void ldsm_x4(uint32_t r[4], uint32_t addr) {
    asm volatile("ldmatrix.sync.aligned.m8n8.x4.shared.b16 {%0,%1,%2,%3}, [%4];"
        : "=r"(r[0]), "=r"(r[1]), "=r"(r[2]), "=r"(r[3]) : "r"(addr));
}
__device__ __forceinline__ void ldsm_x4_t(uint32_t r[4], uint32_t addr) {
    asm volatile("ldmatrix.sync.aligned.m8n8.x4.trans.shared.b16 {%0,%1,%2,%3}, [%4];"
        : "=r"(r[0]), "=r"(r[1]), "=r"(r[2]), "=r"(r[3]) : "r"(addr));
}
__device__ __forceinline__ void mma16816(float c[4], const uint32_t a[4],
                                         const uint32_t b[2]) {
    asm volatile("mma.sync.aligned.m16n8k16.row.col.f32.f16.f16.f32 "
        "{%0,%1,%2,%3}, {%4,%5,%6,%7}, {%8,%9}, {%0,%1,%2,%3};"
        : "+f"(c[0]), "+f"(c[1]), "+f"(c[2]), "+f"(c[3])
        : "r"(a[0]), "r"(a[1]), "r"(a[2]), "r"(a[3]), "r"(b[0]), "r"(b[1]));
}
__device__ __forceinline__ uint32_t pack2h(float x0, float x1) {
    __half2 p = __floats2half2_rn(x0, x1);
    return *(uint32_t*)&p;
}
__device__ __forceinline__ float ex2f(float x) {
    float y;
    asm("ex2.approx.f32 %0, %1;" : "=f"(y) : "f"(x));
    return y;
}

// ---------------------------------------------------------------------------
// Kernel 0: W [1024,128] fp32 -> transposed single fp16 [z][128][1024]
// smem-staged transpose: coalesced reads AND coalesced 16B writes.
// ---------------------------------------------------------------------------
__global__ __launch_bounds__(256) void convert_w_kernel(
    const float* __restrict__ Wq, const float* __restrict__ Wk,
    const float* __restrict__ Wv)
{
    __shared__ __half t[128][136];
    const int z = blockIdx.y, kb = blockIdx.x;
    const float* W = (z == 0) ? Wq : (z == 1) ? Wk : Wv;
    const int tid = threadIdx.x;

    #pragma unroll
    for (int i = 0; i < 64; i++) {
        int u = tid + i * 256;
        int k = u >> 7, n = u & 127;
        t[n][k] = __float2half_rn(W[(size_t)(kb * 128 + k) * H_ + n]);
    }
    __syncthreads();
    #pragma unroll
    for (int i = 0; i < 8; i++) {
        int u = tid + i * 256;
        int n = u >> 4, c = u & 15;
        uint4 v = *(const uint4*)&t[n][c * 8];
        *(uint4*)(g_wt + (size_t)(z * H_ + n) * D_ + kb * 128 + c * 8) = v;
    }
}

// ---------------------------------------------------------------------------
// Kernel 1: QKV projection, single fp16 both operands (A converted in-reg).
// CTA: 128x128, 8 warps, grid interleave (m*3+z) for L2 A-reuse, 2 CTAs/SM.
// ---------------------------------------------------------------------------
#define KST 144
#define QA 0
#define QW 18432
#define QKV_SMEM 36864

__global__ __launch_bounds__(256, 2) void qkv_gemm(const float* __restrict__ A)
{
    extern __shared__ char smc[];
    const uint32_t sb = smem_u32(smc);
    const int tid = threadIdx.x, lane = tid & 31, wid = tid >> 5;
    const int wm = wid >> 1, wn = wid & 1;
    const int m0 = (blockIdx.x / 3) * 128, z = blockIdx.x % 3;
    const int g = lane >> 2, tg = lane & 3;

    const __half* wt = g_wt + (size_t)z * H_ * D_;

    float acc[2][8][4];
    #pragma unroll
    for (int a = 0; a < 2; a++)
        #pragma unroll
        for (int b = 0; b < 8; b++)
            #pragma unroll
            for (int c = 0; c < 4; c++) acc[a][b][c] = 0.f;

    for (int ch = 0; ch < 16; ch++) {
        const int k0 = ch * 64;
        #pragma unroll
        for (int i = 0; i < 4; i++) {
            const int rem = tid + i * 256;
            const int row = rem >> 3, c = rem & 7;
            cp16(sb + QW + row * KST + c * 16,
                 wt + (size_t)row * D_ + k0 + c * 8);
        }
        CP_COMMIT();

        #pragma unroll
        for (int gi = 0; gi < 4; gi++) {
            const int u = tid + gi * 256;
            const int row = u >> 3, c8 = u & 7;
            const float* ap = A + (size_t)(m0 + row) * D_ + k0 + c8 * 8;
            float4 f0 = *(const float4*)ap;
            float4 f1 = *(const float4*)(ap + 4);
            uint4 hv = make_uint4(pack2h(f0.x, f0.y), pack2h(f0.z, f0.w),
                                  pack2h(f1.x, f1.y), pack2h(f1.z, f1.w));
            *(uint4*)(smc + QA + row * KST + c8 * 16) = hv;
        }
        CP_WAIT0();
        __syncthreads();

        #pragma unroll
        for (int s = 0; s < 4; s++) {
            uint32_t af[2][4];
            #pragma unroll
            for (int mt = 0; mt < 2; mt++) {
                uint32_t ar = (uint32_t)((wm * 32 + mt * 16 + (lane & 15)) * KST
                               + (s * 16 + (lane >> 4) * 8) * 2);
                ldsm_x4(af[mt], sb + QA + ar);
            }
            uint32_t bw[4][4];
            #pragma unroll
            for (int p = 0; p < 4; p++) {
                uint32_t br = (uint32_t)((wn * 64 + p * 16 + (lane >> 4) * 8 + (lane & 7)) * KST
                               + (s * 16 + ((lane >> 3) & 1) * 8) * 2);
                ldsm_x4(bw[p], sb + QW + br);
            }
            #pragma unroll
            for (int p = 0; p < 4; p++)
                #pragma unroll
                for (int mt = 0; mt < 2; mt++) {
                    mma16816(acc[mt][2*p],   af[mt], bw[p]);
                    mma16816(acc[mt][2*p+1], af[mt], bw[p] + 2);
                }
        }
        __syncthreads();
    }

    const float scl = (z == 0)
        ? (0.0883883476483184405f * 1.4426950408889634f) : 1.0f;
    __half* dst = (z == 0) ? g_q : (z == 1) ? g_k : g_v;

    #pragma unroll
    for (int mt = 0; mt < 2; mt++)
        #pragma unroll
        for (int nt = 0; nt < 8; nt++) {
            float c0 = acc[mt][nt][0] * scl, c1 = acc[mt][nt][1] * scl;
            float c2 = acc[mt][nt][2] * scl, c3 = acc[mt][nt][3] * scl;
            int r0  = m0 + wm * 32 + mt * 16 + g;
            int col = wn * 64 + nt * 8 + tg * 2;
            *(uint32_t*)(dst + (size_t)r0 * H_ + col)       = pack2h(c0, c1);
            *(uint32_t*)(dst + (size_t)(r0 + 8) * H_ + col) = pack2h(c2, c3);
        }
}

// ---------------------------------------------------------------------------
// Kernel 2: causal flash attention, all-single fp16 operands.
// Grid (B_, 16): blockIdx.x = batch (fastest), blockIdx.y = tile with heavy
// tiles first -> LPT schedule: all 16 heavy CTAs start in wave 1.
// ---------------------------------------------------------------------------
#define QS 272
#define ASTG  34816
#define AK 0
#define AV 17408
#define ATT_SMEM (2*ASTG)        // 69632

__global__ __launch_bounds__(256, 1) void attn_mma(float* __restrict__ out)
{
    extern __shared__ char smc[];
    const uint32_t sb = smem_u32(smc);
    const int tid = threadIdx.x, lane = tid & 31, w = tid >> 5;
    const int b  = blockIdx.x;               // batch fastest
    const int it = 15 - blockIdx.y;          // heavy tiles first
    const int q0 = it * 128;
    const int jmax = 2 * it + 1;
    const int g = lane >> 2, tg = lane & 3;
    const size_t base = (size_t)b * S_ * H_;

    #define ATT_ISSUE_KV(j, st) do {                                          \
        const int t0_ = (j) * 64;                                             \
        const uint32_t s0_ = sb + (st) * ASTG;                                \
        _Pragma("unroll")                                                     \
        for (int i = 0; i < 8; i++) {                                         \
            const int buf = i >> 2;                                           \
            const int rem = tid + (i & 3) * 256;                              \
            const int row = rem >> 4, c = rem & 15;                           \
            uint32_t d = s0_ + buf * 17408 + row * QS + c * 16;               \
            const __half* src = (buf == 0 ? g_k : g_v) + base                 \
                                + (size_t)(t0_ + row) * H_ + c * 8;           \
            cp16(d, src);                                                     \
        }                                                                     \
    } while (0)

    #pragma unroll
    for (int i = 0; i < 8; i++) {
        const int rem = tid + i * 256;
        const int row = rem >> 4, c = rem & 15;
        cp16(sb + row * QS + c * 16,
             g_q + base + (size_t)(q0 + row) * H_ + c * 8);
    }
    CP_COMMIT(); CP_WAIT0();
    __syncthreads();
    uint32_t qf[8][4];
    #pragma unroll
    for (int ks = 0; ks < 8; ks++) {
        uint32_t ar = (uint32_t)((w * 16 + (lane & 15)) * QS
                       + (ks * 16 + (lane >> 4) * 8) * 2);
        ldsm_x4(qf[ks], sb + ar);
    }
    __syncthreads();

    ATT_ISSUE_KV(0, 0); CP_COMMIT();

    float o[16][4];
    #pragma unroll
    for (int f = 0; f < 16; f++)
        #pragma unroll
        for (int c = 0; c < 4; c++) o[f][c] = 0.f;
    float m0r = -INFINITY, m1r = -INFINITY, l0 = 0.f, l1 = 0.f;

    for (int j = 0; j <= jmax; j++) {
        if (j < jmax) { ATT_ISSUE_KV(j + 1, (j + 1) & 1); CP_COMMIT(); CP_WAIT1(); }
        else CP_WAIT0();
        __syncthreads();

        const int t0 = j * 64;
        const uint32_t stb = sb + (j & 1) * ASTG;

        if (t0 <= q0 + w * 16 + 15) {
            float s[8][4];
            #pragma unroll
            for (int nt = 0; nt < 8; nt++)
                #pragma unroll
                for (int c = 0; c < 4; c++) s[nt][c] = 0.f;

            #pragma unroll
            for (int ks = 0; ks < 8; ks++) {
                uint32_t bk[4][4];
                #pragma unroll
                for (int p = 0; p < 4; p++) {
                    uint32_t br = (uint32_t)((p * 16 + (lane >> 4) * 8 + (lane & 7)) * QS
                                   + (ks * 16 + ((lane >> 3) & 1) * 8) * 2);
                    ldsm_x4(bk[p], stb + AK + br);
                }
                #pragma unroll
                for (int p = 0; p < 4; p++) {
                    mma16816(s[2*p],   qf[ks], bk[p]);
                    mma16816(s[2*p+1], qf[ks], bk[p] + 2);
                }
            }

            if (j >= jmax - 1) {
                int r0 = q0 + w * 16 + g, r1 = r0 + 8;
                #pragma unroll
                for (int nt = 0; nt < 8; nt++) {
                    int kc = t0 + nt * 8 + tg * 2;
                    if (kc     > r0) s[nt][0] = -INFINITY;
                    if (kc + 1 > r0) s[nt][1] = -INFINITY;
                    if (kc     > r1) s[nt][2] = -INFINITY;
                    if (kc + 1 > r1) s[nt][3] = -INFINITY;
                }
            }

            float ml0 = -INFINITY, ml1 = -INFINITY;
            #pragma unroll
            for (int nt = 0; nt < 8; nt++) {
                ml0 = fmaxf(ml0, fmaxf(s[nt][0], s[nt][1]));
                ml1 = fmaxf(ml1, fmaxf(s[nt][2], s[nt][3]));
            }
            #pragma unroll
            for (int ofs = 1; ofs <= 2; ofs <<= 1) {
                ml0 = fmaxf(ml0, __shfl_xor_sync(0xffffffffu, ml0, ofs));
                ml1 = fmaxf(ml1, __shfl_xor_sync(0xffffffffu, ml1, ofs));
            }
            float mn0 = fmaxf(m0r, ml0), mn1 = fmaxf(m1r, ml1);
            float a0 = ex2f(m0r - mn0), a1 = ex2f(m1r - mn1);
            m0r = mn0; m1r = mn1;

            float rs0 = 0.f, rs1 = 0.f;
            #pragma unroll
            for (int nt = 0; nt < 8; nt++) {
                s[nt][0] = ex2f(s[nt][0] - mn0); rs0 += s[nt][0];
                s[nt][1] = ex2f(s[nt][1] - mn0); rs0 += s[nt][1];
                s[nt][2] = ex2f(s[nt][2] - mn1); rs1 += s[nt][2];
                s[nt][3] = ex2f(s[nt][3] - mn1); rs1 += s[nt][3];
            }
            l0 = l0 * a0 + rs0;
            l1 = l1 * a1 + rs1;
            #pragma unroll
            for (int f = 0; f < 16; f++) {
                o[f][0] *= a0; o[f][1] *= a0;
                o[f][2] *= a1; o[f][3] *= a1;
            }

            uint32_t pf[4][4];
            #pragma unroll
            for (int s4 = 0; s4 < 4; s4++) {
                pf[s4][0] = pack2h(s[2*s4][0],   s[2*s4][1]);
                pf[s4][1] = pack2h(s[2*s4][2],   s[2*s4][3]);
                pf[s4][2] = pack2h(s[2*s4+1][0], s[2*s4+1][1]);
                pf[s4][3] = pack2h(s[2*s4+1][2], s[2*s4+1][3]);
            }

            #pragma unroll
            for (int s4 = 0; s4 < 4; s4++) {
                #pragma unroll
                for (int half = 0; half < 2; half++) {
                    uint32_t vv[4][4];
                    #pragma unroll
                    for (int p4 = 0; p4 < 4; p4++) {
                        int p = half * 4 + p4;
                        uint32_t vr = (uint32_t)((s4 * 16 + (lane & 7) + ((lane >> 3) & 1) * 8) * QS
                                       + (p * 2 + (lane >> 4)) * 16);
                        ldsm_x4_t(vv[p4], stb + AV + vr);
                    }
                    #pragma unroll
                    for (int p4 = 0; p4 < 4; p4++) {
                        int p = half * 4 + p4;
                        mma16816(o[2*p],   pf[s4], vv[p4]);
                        mma16816(o[2*p+1], pf[s4], vv[p4] + 2);
                    }
                }
            }
        }
        __syncthreads();
    }

    #pragma unroll
    for (int ofs = 1; ofs <= 2; ofs <<= 1) {
        l0 += __shfl_xor_sync(0xffffffffu, l0, ofs);
        l1 += __shfl_xor_sync(0xffffffffu, l1, ofs);
    }
    float i0 = 1.f / l0, i1 = 1.f / l1;
    int r0 = q0 + w * 16 + g;
    #pragma unroll
    for (int f = 0; f < 16; f++) {
        float2 v0 = make_float2(o[f][0] * i0, o[f][1] * i0);
        float2 v1 = make_float2(o[f][2] * i1, o[f][3] * i1);
        *(float2*)(out + base + (size_t)r0 * H_ + f * 8 + tg * 2)       = v0;
        *(float2*)(out + base + (size_t)(r0 + 8) * H_ + f * 8 + tg * 2) = v1;
    }
}

// ---------------------------------------------------------------------------
extern "C" void kernel_launch(void* const* d_in, const int* in_sizes, int n_in,
                              void* d_out, int out_size)
{
    const float* input = (const float*)d_in[0];
    const float* Wq    = (const float*)d_in[1];
    const float* Wk    = (const float*)d_in[2];
    const float* Wv    = (const float*)d_in[3];
    float* out = (float*)d_out;

    cudaFuncSetAttribute(qkv_gemm, cudaFuncAttributeMaxDynamicSharedMemorySize, QKV_SMEM);
    cudaFuncSetAttribute(attn_mma, cudaFuncAttributeMaxDynamicSharedMemorySize, ATT_SMEM);

    convert_w_kernel<<<dim3(8, 3), 256>>>(Wq, Wk, Wv);
    qkv_gemm<<<3 * M_TOT / 128, 256, QKV_SMEM>>>(input);
    attn_mma<<<dim3(B_, 16), 256, ATT_SMEM>>>(out);
}